// round 4
// baseline (speedup 1.0000x reference)
#include <cuda_runtime.h>
#include <math.h>

// ---------------- problem dims ----------------
#define TT        8192
#define INDIM     109
#define HDIM      1024
#define GDIM      4096           // 4*HDIM
#define NBLK      128            // LSTM blocks: 128 * 8 elems = 1024
#define EPB       8              // h-elements per block

// ---------------- device scratch ----------------
__device__ float g_xp[TT * GDIM];                 // 128 MB input projections
__device__ float g_h0[TT * HDIM];                 // 32 MB layer-0 h history
__device__ float g_h1[TT * HDIM];                 // 32 MB layer-1 h history
__device__ __align__(16) float g_hbuf[2][HDIM];   // double-buffered h state
__device__ __align__(16) unsigned g_flag[NBLK];   // per-block progress flags

// ---------------- small helpers ----------------
__device__ __forceinline__ unsigned long long fma2(unsigned long long a,
                                                   unsigned long long b,
                                                   unsigned long long c) {
    unsigned long long d;
    asm("fma.rn.f32x2 %0, %1, %2, %3;" : "=l"(d) : "l"(a), "l"(b), "l"(c));
    return d;
}
__device__ __forceinline__ float2 unpack2(unsigned long long v) {
    float2 f;
    asm("mov.b64 {%0,%1}, %2;" : "=f"(f.x), "=f"(f.y) : "l"(v));
    return f;
}
__device__ __forceinline__ float fast_sigmoid(float x) {
    float e = __expf(-x);
    return __fdividef(1.f, 1.f + e);
}
__device__ __forceinline__ float fast_tanh(float x) {
    float e = __expf(-2.f * x);
    return fmaf(2.f, __fdividef(1.f, 1.f + e), -1.f);
}

__global__ void reset_state_kernel() {
    int i = threadIdx.x;                  // 1024 threads
    g_hbuf[0][i] = 0.f;
    g_hbuf[1][i] = 0.f;
    if (i < NBLK) g_flag[i] = 0u;
}

// ---------------- xp0: [T,109] @ [4096,109]^T + bias ----------------
__global__ __launch_bounds__(256) void gemm_xproj_small(
    const float* __restrict__ A,      // [T][109]
    const float* __restrict__ B,      // [4096][109]
    const float* __restrict__ bias1,
    const float* __restrict__ bias2)
{
    __shared__ float sA[64][113];
    __shared__ float sB[32][113];
    int t0 = blockIdx.x * 64;
    int r0 = blockIdx.y * 32;
    int tid = threadIdx.x;
    int tx = tid & 15;
    int ty = tid >> 4;

    for (int idx = tid; idx < 64 * INDIM; idx += 256) {
        int row = idx / INDIM, k = idx - row * INDIM;
        sA[row][k] = A[(size_t)(t0 + row) * INDIM + k];
    }
    for (int idx = tid; idx < 32 * INDIM; idx += 256) {
        int row = idx / INDIM, k = idx - row * INDIM;
        sB[row][k] = B[(size_t)(r0 + row) * INDIM + k];
    }
    __syncthreads();

    float acc[4][2];
#pragma unroll
    for (int i = 0; i < 4; i++)
#pragma unroll
        for (int j = 0; j < 2; j++) acc[i][j] = 0.f;

    for (int k = 0; k < INDIM; k++) {
        float a[4], b[2];
#pragma unroll
        for (int i = 0; i < 4; i++) a[i] = sA[ty * 4 + i][k];
#pragma unroll
        for (int j = 0; j < 2; j++) b[j] = sB[tx * 2 + j][k];
#pragma unroll
        for (int i = 0; i < 4; i++)
#pragma unroll
            for (int j = 0; j < 2; j++) acc[i][j] = fmaf(a[i], b[j], acc[i][j]);
    }

#pragma unroll
    for (int j = 0; j < 2; j++) {
        int r = r0 + tx * 2 + j;
        float bs = __ldg(&bias1[r]) + __ldg(&bias2[r]);
#pragma unroll
        for (int i = 0; i < 4; i++) {
            int t = t0 + ty * 4 + i;
            g_xp[(size_t)t * GDIM + r] = acc[i][j] + bs;
        }
    }
}

// ---------------- xp1: [T,1024] @ [4096,1024]^T + bias ----------------
__global__ __launch_bounds__(256) void gemm_xproj_big(
    const float* __restrict__ B,      // [4096][1024] = W_ih1
    const float* __restrict__ bias1,
    const float* __restrict__ bias2)
{
    __shared__ float sA[16][132];
    __shared__ float sB[16][132];
    const float* A = g_h0;            // [T][1024]
    int t0 = blockIdx.x * 128;
    int r0 = blockIdx.y * 128;
    int tid = threadIdx.x;
    int tx = tid & 15;
    int ty = tid >> 4;
    int loadrow = tid & 127;
    int loadq   = tid >> 7;

    float acc[8][8];
#pragma unroll
    for (int i = 0; i < 8; i++)
#pragma unroll
        for (int j = 0; j < 8; j++) acc[i][j] = 0.f;

    for (int kc = 0; kc < HDIM; kc += 16) {
        __syncthreads();
#pragma unroll
        for (int f = 0; f < 2; f++) {
            int kq = loadq * 2 + f;
            float4 v = __ldg((const float4*)(A + (size_t)(t0 + loadrow) * HDIM + kc) + kq);
            int kk = kq * 4;
            sA[kk + 0][loadrow] = v.x; sA[kk + 1][loadrow] = v.y;
            sA[kk + 2][loadrow] = v.z; sA[kk + 3][loadrow] = v.w;
            float4 w = __ldg((const float4*)(B + (size_t)(r0 + loadrow) * HDIM + kc) + kq);
            sB[kk + 0][loadrow] = w.x; sB[kk + 1][loadrow] = w.y;
            sB[kk + 2][loadrow] = w.z; sB[kk + 3][loadrow] = w.w;
        }
        __syncthreads();
#pragma unroll
        for (int k = 0; k < 16; k++) {
            float4 a0 = *(const float4*)&sA[k][ty * 8];
            float4 a1 = *(const float4*)&sA[k][ty * 8 + 4];
            float4 b0 = *(const float4*)&sB[k][tx * 8];
            float4 b1 = *(const float4*)&sB[k][tx * 8 + 4];
            float a[8] = {a0.x, a0.y, a0.z, a0.w, a1.x, a1.y, a1.z, a1.w};
            float b[8] = {b0.x, b0.y, b0.z, b0.w, b1.x, b1.y, b1.z, b1.w};
#pragma unroll
            for (int i = 0; i < 8; i++)
#pragma unroll
                for (int j = 0; j < 8; j++) acc[i][j] = fmaf(a[i], b[j], acc[i][j]);
        }
    }

    float bs[8];
#pragma unroll
    for (int j = 0; j < 8; j++) {
        int r = r0 + tx * 8 + j;
        bs[j] = __ldg(&bias1[r]) + __ldg(&bias2[r]);
    }
#pragma unroll
    for (int i = 0; i < 8; i++) {
        int t = t0 + ty * 8 + i;
        float* crow = g_xp + (size_t)t * GDIM + r0 + tx * 8;
        float4 o0 = make_float4(acc[i][0] + bs[0], acc[i][1] + bs[1],
                                acc[i][2] + bs[2], acc[i][3] + bs[3]);
        float4 o1 = make_float4(acc[i][4] + bs[4], acc[i][5] + bs[5],
                                acc[i][6] + bs[6], acc[i][7] + bs[7]);
        *(float4*)crow = o0;
        *(float4*)(crow + 4) = o1;
    }
}

// ---------------- LSTM recurrence: persistent, flag-synced ----------------
// 128 blocks x 256 threads. Block b owns h elems [8b, 8b+8).
// Warp j (0..7) owns ALL FOUR gate rows of element e = 8b + j:
//   rows g*1024 + 8b + j, g = 0..3  (i,f,g,o)
// Lane l holds column-quads {l+32k : k=0..7}. After shfl reduce, lane 0 has
// all 4 dots -> gate math + publish entirely in-warp (no sDot round trip).
// No __threadfence: h publish via st.cg; __syncthreads; flag via st.release.
__global__ __launch_bounds__(256, 1) void lstm_layer_kernel(
    const float* __restrict__ Whh,    // [4096][1024]
    int out_sel)                      // 0 -> g_h0, 1 -> g_h1
{
    __shared__ float4 sH4[256];       // h staging (4KB)

    float* hout = out_sel ? g_h1 : g_h0;
    int b   = blockIdx.x;
    int tid = threadIdx.x;
    int w   = tid >> 5;               // warp = owned h element (within block)
    int l   = tid & 31;
    int e   = (b << 3) + w;           // global h element index

    // ---- load this warp's 4 gate rows into registers ----
    ulonglong2 Wreg[4][8];
#pragma unroll
    for (int g = 0; g < 4; g++) {
        const ulonglong2* rowp =
            (const ulonglong2*)(Whh + (size_t)((g << 10) + e) * HDIM);
#pragma unroll
        for (int k = 0; k < 8; k++) Wreg[g][k] = rowp[l + 32 * k];
    }
    float creg = 0.f;                 // cell state (lane 0 only meaningful)

    const uint4* flags4 = (const uint4*)g_flag;

    // prefetch xp for t=0
    float x0 = 0.f, x1 = 0.f, x2 = 0.f, x3 = 0.f;
    if (l == 0) {
        const float* p = g_xp + e;
        x0 = __ldg(p);
        x1 = __ldg(p + 1024);
        x2 = __ldg(p + 2048);
        x3 = __ldg(p + 3072);
    }

    for (int t = 0; t < TT; t++) {
        // prefetch xp for NEXT step (consumed a full step later -> hidden)
        float nx0 = 0.f, nx1 = 0.f, nx2 = 0.f, nx3 = 0.f;
        if (l == 0 && t + 1 < TT) {
            const float* p = g_xp + (size_t)(t + 1) * GDIM + e;
            nx0 = __ldg(p);
            nx1 = __ldg(p + 1024);
            nx2 = __ldg(p + 2048);
            nx3 = __ldg(p + 3072);
        }

        // every warp polls all 128 flags until h_t is fully published
        if (t) {
            unsigned need = (unsigned)t;
            bool ok;
            do {
                uint4 v;
                asm volatile(
                    "ld.acquire.gpu.global.v4.u32 {%0,%1,%2,%3}, [%4];"
                    : "=r"(v.x), "=r"(v.y), "=r"(v.z), "=r"(v.w)
                    : "l"(flags4 + l) : "memory");
                ok = v.x >= need && v.y >= need && v.z >= need && v.w >= need;
            } while (!__all_sync(0xffffffffu, ok));
        }

        // stage h_t into SMEM (each warp ordered by its own acquire)
        sH4[tid] = __ldcg(((const float4*)g_hbuf[t & 1]) + tid);
        __syncthreads();

        // matvec: 4 gate rows x 32 col-quads per thread, packed f32x2 FMA
        const ulonglong2* sH2 = (const ulonglong2*)sH4;
        unsigned long long acc[4][2];
#pragma unroll
        for (int g = 0; g < 4; g++) { acc[g][0] = 0ull; acc[g][1] = 0ull; }
#pragma unroll
        for (int k = 0; k < 8; k++) {
            ulonglong2 hv = sH2[32 * k + l];    // conflict-free LDS.128
#pragma unroll
            for (int g = 0; g < 4; g++) {
                acc[g][0] = fma2(Wreg[g][k].x, hv.x, acc[g][0]);
                acc[g][1] = fma2(Wreg[g][k].y, hv.y, acc[g][1]);
            }
        }
        float dot[4];
#pragma unroll
        for (int g = 0; g < 4; g++) {
            float2 lo = unpack2(acc[g][0]);
            float2 hi = unpack2(acc[g][1]);
            float s = (lo.x + lo.y) + (hi.x + hi.y);
#pragma unroll
            for (int off = 16; off; off >>= 1)
                s += __shfl_xor_sync(0xffffffffu, s, off);
            dot[g] = s;
        }

        // gate math + publish h_{t+1} (lane 0 of each warp)
        if (l == 0) {
            float gi = dot[0] + x0;
            float gf = dot[1] + x1;
            float gg = dot[2] + x2;
            float go = dot[3] + x3;
            float si = fast_sigmoid(gi);
            float sf = fast_sigmoid(gf);
            float so = fast_sigmoid(go);
            float tg = fast_tanh(gg);
            float c  = fmaf(sf, creg, si * tg);
            creg = c;
            float h  = so * fast_tanh(c);
            __stcg(&g_hbuf[(t + 1) & 1][e], h);       // L2 publish
            hout[(size_t)t * HDIM + e] = h;           // DRAM history (no fence)
        }
        __syncthreads();            // orders h publish before flag release
        if (tid == 0) {
            unsigned nv = (unsigned)(t + 1);
            asm volatile("st.release.gpu.global.u32 [%0], %1;"
                         :: "l"(&g_flag[b]), "r"(nv) : "memory");
        }

        x0 = nx0; x1 = nx1; x2 = nx2; x3 = nx3;
    }
}

// ---------------- FC + log_softmax ----------------
__global__ __launch_bounds__(128) void fc_logsoftmax_kernel(
    const float* __restrict__ fcw,    // [109][1024]
    const float* __restrict__ fcb,    // [109]
    float* __restrict__ out)          // [T][109]
{
    __shared__ float sH[8 * 1024];
    __shared__ float sL[8][112];
    __shared__ float sLse[8];
    int t0 = blockIdx.x * 8;
    int tid = threadIdx.x;

    const float4* hg = (const float4*)(g_h1 + (size_t)t0 * HDIM);
    float4* sH4 = (float4*)sH;
#pragma unroll
    for (int q = 0; q < 16; q++) sH4[tid + 128 * q] = __ldg(hg + tid + 128 * q);
    __syncthreads();

    if (tid < INDIM) {
        float acc[8];
#pragma unroll
        for (int i = 0; i < 8; i++) acc[i] = 0.f;
        const float4* w4 = (const float4*)(fcw + (size_t)tid * HDIM);
        for (int k4 = 0; k4 < 256; k4++) {
            float4 w = __ldg(w4 + k4);
#pragma unroll
            for (int tt = 0; tt < 8; tt++) {
                float4 hv = sH4[tt * 256 + k4];
                acc[tt] = fmaf(w.x, hv.x,
                          fmaf(w.y, hv.y,
                          fmaf(w.z, hv.z,
                          fmaf(w.w, hv.w, acc[tt]))));
            }
        }
        float bb = __ldg(&fcb[tid]);
#pragma unroll
        for (int tt = 0; tt < 8; tt++) sL[tt][tid] = acc[tt] + bb;
    }
    __syncthreads();

    if (tid < 8) {
        float m = -1e30f;
        for (int n = 0; n < INDIM; n++) m = fmaxf(m, sL[tid][n]);
        float s = 0.f;
        for (int n = 0; n < INDIM; n++) s += expf(sL[tid][n] - m);
        sLse[tid] = m + logf(s);
    }
    __syncthreads();

    for (int idx = tid; idx < 8 * INDIM; idx += 128) {
        int tt = idx / INDIM, n = idx - tt * INDIM;
        out[(size_t)(t0 + tt) * INDIM + n] = sL[tt][n] - sLse[tt];
    }
}

// ---------------- launcher ----------------
extern "C" void kernel_launch(void* const* d_in, const int* in_sizes, int n_in,
                              void* d_out, int out_size) {
    const float* input = (const float*)d_in[0];
    const float* W_ih0 = (const float*)d_in[1];
    const float* W_hh0 = (const float*)d_in[2];
    const float* b_ih0 = (const float*)d_in[3];
    const float* b_hh0 = (const float*)d_in[4];
    const float* W_ih1 = (const float*)d_in[5];
    const float* W_hh1 = (const float*)d_in[6];
    const float* b_ih1 = (const float*)d_in[7];
    const float* b_hh1 = (const float*)d_in[8];
    const float* fc_w  = (const float*)d_in[9];
    const float* fc_b  = (const float*)d_in[10];
    float* out = (float*)d_out;

    // xp0 = input @ W_ih0^T + b_ih0 + b_hh0
    gemm_xproj_small<<<dim3(TT / 64, GDIM / 32), 256>>>(input, W_ih0, b_ih0, b_hh0);

    // layer 0 recurrence -> g_h0
    reset_state_kernel<<<1, 1024>>>();
    lstm_layer_kernel<<<NBLK, 256>>>(W_hh0, 0);

    // xp1 = h0 @ W_ih1^T + b_ih1 + b_hh1
    gemm_xproj_big<<<dim3(TT / 128, GDIM / 128), 256>>>(W_ih1, b_ih1, b_hh1);

    // layer 1 recurrence -> g_h1
    reset_state_kernel<<<1, 1024>>>();
    lstm_layer_kernel<<<NBLK, 256>>>(W_hh1, 1);

    // logits + log_softmax
    fc_logsoftmax_kernel<<<TT / 8, 128>>>(fc_w, fc_b, out);
}

// round 5
// speedup vs baseline: 3.6666x; 3.6666x over previous
#include <cuda_runtime.h>
#include <math.h>

// ---------------- problem dims ----------------
#define TT        8192
#define INDIM     109
#define HDIM      1024
#define GDIM      4096           // 4*HDIM
#define NBLK      128            // LSTM blocks: 128 * 8 elems = 1024
#define EPB       8              // h-elements per block

// ---------------- device scratch ----------------
__device__ float g_xp[TT * GDIM];                 // 128 MB input projections
__device__ float g_h0[TT * HDIM];                 // 32 MB layer-0 h history
__device__ float g_h1[TT * HDIM];                 // 32 MB layer-1 h history
__device__ __align__(16) float g_hbuf[2][HDIM];   // double-buffered h state
__device__ __align__(16) unsigned g_flag[NBLK];   // per-block progress flags

// ---------------- small helpers ----------------
__device__ __forceinline__ unsigned long long fma2(unsigned long long a,
                                                   unsigned long long b,
                                                   unsigned long long c) {
    unsigned long long d;
    asm("fma.rn.f32x2 %0, %1, %2, %3;" : "=l"(d) : "l"(a), "l"(b), "l"(c));
    return d;
}
__device__ __forceinline__ float2 unpack2(unsigned long long v) {
    float2 f;
    asm("mov.b64 {%0,%1}, %2;" : "=f"(f.x), "=f"(f.y) : "l"(v));
    return f;
}
__device__ __forceinline__ float fast_sigmoid(float x) {
    float e = __expf(-x);
    return __fdividef(1.f, 1.f + e);
}
__device__ __forceinline__ float fast_tanh(float x) {
    float e = __expf(-2.f * x);
    return fmaf(2.f, __fdividef(1.f, 1.f + e), -1.f);
}

__global__ void reset_state_kernel() {
    int i = threadIdx.x;                  // 1024 threads
    g_hbuf[0][i] = 0.f;
    g_hbuf[1][i] = 0.f;
    if (i < NBLK) g_flag[i] = 0u;
}

// ---------------- xp0: [T,109] @ [4096,109]^T + bias ----------------
__global__ __launch_bounds__(256) void gemm_xproj_small(
    const float* __restrict__ A,      // [T][109]
    const float* __restrict__ B,      // [4096][109]
    const float* __restrict__ bias1,
    const float* __restrict__ bias2)
{
    __shared__ float sA[64][113];
    __shared__ float sB[32][113];
    int t0 = blockIdx.x * 64;
    int r0 = blockIdx.y * 32;
    int tid = threadIdx.x;
    int tx = tid & 15;
    int ty = tid >> 4;

    for (int idx = tid; idx < 64 * INDIM; idx += 256) {
        int row = idx / INDIM, k = idx - row * INDIM;
        sA[row][k] = A[(size_t)(t0 + row) * INDIM + k];
    }
    for (int idx = tid; idx < 32 * INDIM; idx += 256) {
        int row = idx / INDIM, k = idx - row * INDIM;
        sB[row][k] = B[(size_t)(r0 + row) * INDIM + k];
    }
    __syncthreads();

    float acc[4][2];
#pragma unroll
    for (int i = 0; i < 4; i++)
#pragma unroll
        for (int j = 0; j < 2; j++) acc[i][j] = 0.f;

    for (int k = 0; k < INDIM; k++) {
        float a[4], b[2];
#pragma unroll
        for (int i = 0; i < 4; i++) a[i] = sA[ty * 4 + i][k];
#pragma unroll
        for (int j = 0; j < 2; j++) b[j] = sB[tx * 2 + j][k];
#pragma unroll
        for (int i = 0; i < 4; i++)
#pragma unroll
            for (int j = 0; j < 2; j++) acc[i][j] = fmaf(a[i], b[j], acc[i][j]);
    }

#pragma unroll
    for (int j = 0; j < 2; j++) {
        int r = r0 + tx * 2 + j;
        float bs = __ldg(&bias1[r]) + __ldg(&bias2[r]);
#pragma unroll
        for (int i = 0; i < 4; i++) {
            int t = t0 + ty * 4 + i;
            g_xp[(size_t)t * GDIM + r] = acc[i][j] + bs;
        }
    }
}

// ---------------- xp1: [T,1024] @ [4096,1024]^T + bias ----------------
__global__ __launch_bounds__(256) void gemm_xproj_big(
    const float* __restrict__ B,      // [4096][1024] = W_ih1
    const float* __restrict__ bias1,
    const float* __restrict__ bias2)
{
    __shared__ float sA[16][132];
    __shared__ float sB[16][132];
    const float* A = g_h0;            // [T][1024]
    int t0 = blockIdx.x * 128;
    int r0 = blockIdx.y * 128;
    int tid = threadIdx.x;
    int tx = tid & 15;
    int ty = tid >> 4;
    int loadrow = tid & 127;
    int loadq   = tid >> 7;

    float acc[8][8];
#pragma unroll
    for (int i = 0; i < 8; i++)
#pragma unroll
        for (int j = 0; j < 8; j++) acc[i][j] = 0.f;

    for (int kc = 0; kc < HDIM; kc += 16) {
        __syncthreads();
#pragma unroll
        for (int f = 0; f < 2; f++) {
            int kq = loadq * 2 + f;
            float4 v = __ldg((const float4*)(A + (size_t)(t0 + loadrow) * HDIM + kc) + kq);
            int kk = kq * 4;
            sA[kk + 0][loadrow] = v.x; sA[kk + 1][loadrow] = v.y;
            sA[kk + 2][loadrow] = v.z; sA[kk + 3][loadrow] = v.w;
            float4 w = __ldg((const float4*)(B + (size_t)(r0 + loadrow) * HDIM + kc) + kq);
            sB[kk + 0][loadrow] = w.x; sB[kk + 1][loadrow] = w.y;
            sB[kk + 2][loadrow] = w.z; sB[kk + 3][loadrow] = w.w;
        }
        __syncthreads();
#pragma unroll
        for (int k = 0; k < 16; k++) {
            float4 a0 = *(const float4*)&sA[k][ty * 8];
            float4 a1 = *(const float4*)&sA[k][ty * 8 + 4];
            float4 b0 = *(const float4*)&sB[k][tx * 8];
            float4 b1 = *(const float4*)&sB[k][tx * 8 + 4];
            float a[8] = {a0.x, a0.y, a0.z, a0.w, a1.x, a1.y, a1.z, a1.w};
            float b[8] = {b0.x, b0.y, b0.z, b0.w, b1.x, b1.y, b1.z, b1.w};
#pragma unroll
            for (int i = 0; i < 8; i++)
#pragma unroll
                for (int j = 0; j < 8; j++) acc[i][j] = fmaf(a[i], b[j], acc[i][j]);
        }
    }

    float bs[8];
#pragma unroll
    for (int j = 0; j < 8; j++) {
        int r = r0 + tx * 8 + j;
        bs[j] = __ldg(&bias1[r]) + __ldg(&bias2[r]);
    }
#pragma unroll
    for (int i = 0; i < 8; i++) {
        int t = t0 + ty * 8 + i;
        float* crow = g_xp + (size_t)t * GDIM + r0 + tx * 8;
        float4 o0 = make_float4(acc[i][0] + bs[0], acc[i][1] + bs[1],
                                acc[i][2] + bs[2], acc[i][3] + bs[3]);
        float4 o1 = make_float4(acc[i][4] + bs[4], acc[i][5] + bs[5],
                                acc[i][6] + bs[6], acc[i][7] + bs[7]);
        *(float4*)crow = o0;
        *(float4*)(crow + 4) = o1;
    }
}

// ---------------- LSTM recurrence: persistent, flag-synced ----------------
// 128 blocks x 256 threads. Block b owns h elems [8b, 8b+8).
// Warp j (0..7) owns ALL FOUR gate rows of element e = 8b + j.
// Lane l holds column-quads {l+32k : k=0..7}. Lane 0 does gate math.
// ONLY WARP 0 polls the flags (R3-proven: 128 polling warps chip-wide is
// benign; 1024 pollers in R4 collapsed L2). Readiness broadcast via bar.
// No __threadfence: h publish via st.cg; bar; flag via st.release (cumulative).
__global__ __launch_bounds__(256, 1) void lstm_layer_kernel(
    const float* __restrict__ Whh,    // [4096][1024]
    int out_sel)                      // 0 -> g_h0, 1 -> g_h1
{
    __shared__ float4 sH4[256];       // h staging (4KB)

    float* hout = out_sel ? g_h1 : g_h0;
    int b   = blockIdx.x;
    int tid = threadIdx.x;
    int w   = tid >> 5;               // warp = owned h element (within block)
    int l   = tid & 31;
    int e   = (b << 3) + w;           // global h element index

    // ---- load this warp's 4 gate rows into registers ----
    ulonglong2 Wreg[4][8];
#pragma unroll
    for (int g = 0; g < 4; g++) {
        const ulonglong2* rowp =
            (const ulonglong2*)(Whh + (size_t)((g << 10) + e) * HDIM);
#pragma unroll
        for (int k = 0; k < 8; k++) Wreg[g][k] = rowp[l + 32 * k];
    }
    float creg = 0.f;                 // cell state (lane 0 only meaningful)

    const uint4* flags4 = (const uint4*)g_flag;

    // prefetch xp for t=0
    float x0 = 0.f, x1 = 0.f, x2 = 0.f, x3 = 0.f;
    if (l == 0) {
        const float* p = g_xp + e;
        x0 = __ldg(p);
        x1 = __ldg(p + 1024);
        x2 = __ldg(p + 2048);
        x3 = __ldg(p + 3072);
    }

    for (int t = 0; t < TT; t++) {
        // prefetch xp for NEXT step (consumed a full step later -> hidden)
        float nx0 = 0.f, nx1 = 0.f, nx2 = 0.f, nx3 = 0.f;
        if (l == 0 && t + 1 < TT) {
            const float* p = g_xp + (size_t)(t + 1) * GDIM + e;
            nx0 = __ldg(p);
            nx1 = __ldg(p + 1024);
            nx2 = __ldg(p + 2048);
            nx3 = __ldg(p + 3072);
        }

        // warp 0 polls all 128 flags until h_t fully published; bar broadcasts
        if (t) {
            if (w == 0) {
                unsigned need = (unsigned)t;
                bool ok;
                do {
                    uint4 v;
                    asm volatile(
                        "ld.acquire.gpu.global.v4.u32 {%0,%1,%2,%3}, [%4];"
                        : "=r"(v.x), "=r"(v.y), "=r"(v.z), "=r"(v.w)
                        : "l"(flags4 + l) : "memory");
                    ok = v.x >= need && v.y >= need && v.z >= need && v.w >= need;
                } while (!__all_sync(0xffffffffu, ok));
            }
            __syncthreads();          // broadcast readiness (acquire in warp 0)
        }

        // stage h_t into SMEM (L2-coherent loads)
        sH4[tid] = __ldcg(((const float4*)g_hbuf[t & 1]) + tid);
        __syncthreads();

        // matvec: 4 gate rows x 32 col-quads per thread, packed f32x2 FMA
        const ulonglong2* sH2 = (const ulonglong2*)sH4;
        unsigned long long acc[4][2];
#pragma unroll
        for (int g = 0; g < 4; g++) { acc[g][0] = 0ull; acc[g][1] = 0ull; }
#pragma unroll
        for (int k = 0; k < 8; k++) {
            ulonglong2 hv = sH2[32 * k + l];    // conflict-free LDS.128
#pragma unroll
            for (int g = 0; g < 4; g++) {
                acc[g][0] = fma2(Wreg[g][k].x, hv.x, acc[g][0]);
                acc[g][1] = fma2(Wreg[g][k].y, hv.y, acc[g][1]);
            }
        }
        float dot[4];
#pragma unroll
        for (int g = 0; g < 4; g++) {
            float2 lo = unpack2(acc[g][0]);
            float2 hi = unpack2(acc[g][1]);
            float s = (lo.x + lo.y) + (hi.x + hi.y);
#pragma unroll
            for (int off = 16; off; off >>= 1)
                s += __shfl_xor_sync(0xffffffffu, s, off);
            dot[g] = s;
        }

        // gate math + publish h_{t+1} (lane 0 of each warp)
        if (l == 0) {
            float gi = dot[0] + x0;
            float gf = dot[1] + x1;
            float gg = dot[2] + x2;
            float go = dot[3] + x3;
            float si = fast_sigmoid(gi);
            float sf = fast_sigmoid(gf);
            float so = fast_sigmoid(go);
            float tg = fast_tanh(gg);
            float c  = fmaf(sf, creg, si * tg);
            creg = c;
            float h  = so * fast_tanh(c);
            __stcg(&g_hbuf[(t + 1) & 1][e], h);       // L2 publish
            __stcg(&hout[(size_t)t * HDIM + e], h);   // DRAM history (no fence)
        }
        __syncthreads();            // orders h publish before flag release
        if (tid == 0) {
            unsigned nv = (unsigned)(t + 1);
            asm volatile("st.release.gpu.global.u32 [%0], %1;"
                         :: "l"(&g_flag[b]), "r"(nv) : "memory");
        }

        x0 = nx0; x1 = nx1; x2 = nx2; x3 = nx3;
    }
}

// ---------------- FC + log_softmax ----------------
__global__ __launch_bounds__(128) void fc_logsoftmax_kernel(
    const float* __restrict__ fcw,    // [109][1024]
    const float* __restrict__ fcb,    // [109]
    float* __restrict__ out)          // [T][109]
{
    __shared__ float sH[8 * 1024];
    __shared__ float sL[8][112];
    __shared__ float sLse[8];
    int t0 = blockIdx.x * 8;
    int tid = threadIdx.x;

    const float4* hg = (const float4*)(g_h1 + (size_t)t0 * HDIM);
    float4* sH4 = (float4*)sH;
#pragma unroll
    for (int q = 0; q < 16; q++) sH4[tid + 128 * q] = __ldg(hg + tid + 128 * q);
    __syncthreads();

    if (tid < INDIM) {
        float acc[8];
#pragma unroll
        for (int i = 0; i < 8; i++) acc[i] = 0.f;
        const float4* w4 = (const float4*)(fcw + (size_t)tid * HDIM);
        for (int k4 = 0; k4 < 256; k4++) {
            float4 w = __ldg(w4 + k4);
#pragma unroll
            for (int tt = 0; tt < 8; tt++) {
                float4 hv = sH4[tt * 256 + k4];
                acc[tt] = fmaf(w.x, hv.x,
                          fmaf(w.y, hv.y,
                          fmaf(w.z, hv.z,
                          fmaf(w.w, hv.w, acc[tt]))));
            }
        }
        float bb = __ldg(&fcb[tid]);
#pragma unroll
        for (int tt = 0; tt < 8; tt++) sL[tt][tid] = acc[tt] + bb;
    }
    __syncthreads();

    if (tid < 8) {
        float m = -1e30f;
        for (int n = 0; n < INDIM; n++) m = fmaxf(m, sL[tid][n]);
        float s = 0.f;
        for (int n = 0; n < INDIM; n++) s += expf(sL[tid][n] - m);
        sLse[tid] = m + logf(s);
    }
    __syncthreads();

    for (int idx = tid; idx < 8 * INDIM; idx += 128) {
        int tt = idx / INDIM, n = idx - tt * INDIM;
        out[(size_t)(t0 + tt) * INDIM + n] = sL[tt][n] - sLse[tt];
    }
}

// ---------------- launcher ----------------
extern "C" void kernel_launch(void* const* d_in, const int* in_sizes, int n_in,
                              void* d_out, int out_size) {
    const float* input = (const float*)d_in[0];
    const float* W_ih0 = (const float*)d_in[1];
    const float* W_hh0 = (const float*)d_in[2];
    const float* b_ih0 = (const float*)d_in[3];
    const float* b_hh0 = (const float*)d_in[4];
    const float* W_ih1 = (const float*)d_in[5];
    const float* W_hh1 = (const float*)d_in[6];
    const float* b_ih1 = (const float*)d_in[7];
    const float* b_hh1 = (const float*)d_in[8];
    const float* fc_w  = (const float*)d_in[9];
    const float* fc_b  = (const float*)d_in[10];
    float* out = (float*)d_out;

    // xp0 = input @ W_ih0^T + b_ih0 + b_hh0
    gemm_xproj_small<<<dim3(TT / 64, GDIM / 32), 256>>>(input, W_ih0, b_ih0, b_hh0);

    // layer 0 recurrence -> g_h0
    reset_state_kernel<<<1, 1024>>>();
    lstm_layer_kernel<<<NBLK, 256>>>(W_hh0, 0);

    // xp1 = h0 @ W_ih1^T + b_ih1 + b_hh1
    gemm_xproj_big<<<dim3(TT / 128, GDIM / 128), 256>>>(W_ih1, b_ih1, b_hh1);

    // layer 1 recurrence -> g_h1
    reset_state_kernel<<<1, 1024>>>();
    lstm_layer_kernel<<<NBLK, 256>>>(W_hh1, 1);

    // logits + log_softmax
    fc_logsoftmax_kernel<<<TT / 8, 128>>>(fc_w, fc_b, out);
}